// round 7
// baseline (speedup 1.0000x reference)
#include <cuda_runtime.h>
#include <math.h>
#include <stdint.h>

// ---------------- problem constants ----------------
#define NE 40000
#define NN 10000
#define NFULL 25          // (LMAX+1)^2
#define NM 19             // NUM_M
#define MSG1_W 2432       // 19*128
#define H1_W 1216         // 19*64
#define RAD_W 1536
#define OUT_ELEMS (NN * NFULL * 64)

// ---------------- static scratch (allowed: __device__ globals) ----------------
static __device__ float g_t64a[(size_t)NE * 64];
static __device__ float g_t64b[(size_t)NE * 64];
static __device__ float g_rad [(size_t)NE * RAD_W];
static __device__ float g_msg1[(size_t)NE * MSG1_W];
static __device__ float g_t576[(size_t)NE * 576];
static __device__ float g_y0  [(size_t)NE * 512];
static __device__ float g_y1  [(size_t)NE * 512];
static __device__ float g_z0  [(size_t)NE * 384];
static __device__ float g_z1  [(size_t)NE * 384];
static __device__ float g_h1  [(size_t)NE * H1_W];
static __device__ float g_t320[(size_t)NE * 320];
static __device__ float g_msg2[(size_t)NE * H1_W];

// ---------------- helpers ----------------
__device__ __forceinline__ float sigmoidf_(float x) { return 1.0f / (1.0f + expf(-x)); }
__device__ __forceinline__ float siluf_(float x)    { return x / (1.0f + expf(-x)); }

// ---------------- zero fill ----------------
__global__ void zero_kernel(float* p, int n) {
    int i = blockIdx.x * blockDim.x + threadIdx.x;
    if (i < n) p[i] = 0.0f;
}

// ---------------- generic tiled GEMM: C[M=NE,N] = A[M,K](lda) @ W[K,N] (+bias) ----------------
// Requires: M % 64 == 0, N % 64 == 0, K % 16 == 0, lda % 4 == 0, base ptrs 16B-aligned.
__global__ void __launch_bounds__(256) gemm64(
    const float* __restrict__ A, int lda,
    const float* __restrict__ W, int N, int K,
    const float* __restrict__ bias,
    float* __restrict__ C, int ldc)
{
    __shared__ __align__(16) float As[16][68];   // [k][m], padded
    __shared__ __align__(16) float Bs[16][64];   // [k][n]

    int tid = threadIdx.x;
    int tx = tid & 15;          // n-tile coord (4 cols each)
    int ty = tid >> 4;          // m-tile coord (4 rows each)
    int m0 = blockIdx.y * 64;
    int n0 = blockIdx.x * 64;

    // A tile loader: thread -> row ar, float4 at col ac
    int ar = tid >> 2;            // 0..63
    int ac = (tid & 3) * 4;       // 0,4,8,12
    // B tile loader: thread -> row wr, float4 at col wc
    int wr = tid >> 4;            // 0..15
    int wc = (tid & 15) * 4;      // 0..60

    const float* Ap = A + (size_t)(m0 + ar) * lda + ac;

    float acc[4][4];
#pragma unroll
    for (int i = 0; i < 4; i++)
#pragma unroll
        for (int j = 0; j < 4; j++) acc[i][j] = 0.0f;

    for (int k0 = 0; k0 < K; k0 += 16) {
        float4 av = *(const float4*)(Ap + k0);
        float4 bv = *(const float4*)(W + (size_t)(k0 + wr) * N + n0 + wc);
        As[ac + 0][ar] = av.x;
        As[ac + 1][ar] = av.y;
        As[ac + 2][ar] = av.z;
        As[ac + 3][ar] = av.w;
        *(float4*)&Bs[wr][wc] = bv;
        __syncthreads();
#pragma unroll
        for (int kk = 0; kk < 16; kk++) {
            float4 a = *(const float4*)&As[kk][ty * 4];
            float4 b = *(const float4*)&Bs[kk][tx * 4];
            float av_[4] = {a.x, a.y, a.z, a.w};
            float bv_[4] = {b.x, b.y, b.z, b.w};
#pragma unroll
            for (int i = 0; i < 4; i++)
#pragma unroll
                for (int j = 0; j < 4; j++)
                    acc[i][j] += av_[i] * bv_[j];
        }
        __syncthreads();
    }

    float bb[4] = {0.f, 0.f, 0.f, 0.f};
    if (bias) {
#pragma unroll
        for (int j = 0; j < 4; j++) bb[j] = bias[n0 + tx * 4 + j];
    }
#pragma unroll
    for (int i = 0; i < 4; i++) {
        float* Cp = C + (size_t)(m0 + ty * 4 + i) * ldc + n0 + tx * 4;
#pragma unroll
        for (int j = 0; j < 4; j++) Cp[j] = acc[i][j] + bb[j];
    }
}

// ---------------- LayerNorm + SiLU over 64 channels, in-place ----------------
__global__ void lnsilu_kernel(float* __restrict__ h,
                              const float* __restrict__ g,
                              const float* __restrict__ b)
{
    int e = blockIdx.x;
    int t = threadIdx.x;   // 64 threads
    float v = h[(size_t)e * 64 + t];

    __shared__ float red[4];
    float s = v;
#pragma unroll
    for (int o = 16; o > 0; o >>= 1) s += __shfl_xor_sync(0xffffffffu, s, o);
    if ((t & 31) == 0) red[t >> 5] = s;
    __syncthreads();
    float mu = (red[0] + red[1]) * (1.0f / 64.0f);

    float d = v - mu;
    float s2 = d * d;
#pragma unroll
    for (int o = 16; o > 0; o >>= 1) s2 += __shfl_xor_sync(0xffffffffu, s2, o);
    if ((t & 31) == 0) red[2 + (t >> 5)] = s2;
    __syncthreads();
    float var = (red[2] + red[3]) * (1.0f / 64.0f);

    float y = d * rsqrtf(var + 1e-5f) * g[t] + b[t];
    h[(size_t)e * 64 + t] = siluf_(y);
}

// ---------------- wigner forward: msg1[e] = (wigner[e] @ concat(x[src],x[dst])) * radscale ----------------
__global__ void __launch_bounds__(256) wig_fwd_kernel(
    const float* __restrict__ x,
    const int* __restrict__ edge_index,
    const float* __restrict__ wigner,
    const float* __restrict__ rad,
    float* __restrict__ msg1)
{
    int e = blockIdx.x;
    int tid = threadIdx.x;
    __shared__ float sw[NM * NFULL];      // 475
    __shared__ float sx[NFULL * 128];     // 3200

    int src = edge_index[e];
    int dst = edge_index[NE + e];

    const float* wp = wigner + (size_t)e * (NM * NFULL);
    for (int i = tid; i < NM * NFULL; i += 256) sw[i] = wp[i];

    const float* xs = x + (size_t)src * (NFULL * 64);
    const float* xd = x + (size_t)dst * (NFULL * 64);
    for (int i = tid; i < NFULL * 64; i += 256) {
        int k = i >> 6, c = i & 63;
        sx[k * 128 + c]       = xs[i];
        sx[k * 128 + 64 + c]  = xd[i];
    }
    __syncthreads();

    float* mp = msg1 + (size_t)e * MSG1_W;
    const float* rp = rad + (size_t)e * RAD_W;
    for (int o = tid; o < MSG1_W; o += 256) {
        int r = o >> 7, f = o & 127;
        float s = 0.0f;
        const float* wrow = &sw[r * NFULL];
#pragma unroll
        for (int k = 0; k < NFULL; k++) s += wrow[k] * sx[k * 128 + f];
        int sidx;
        if (r < 5)        sidx = r * 128 + f;
        else if (r < 13)  sidx = 640  + ((r - 5) & 3) * 128 + f;
        else              sidx = 1152 + ((r - 13) % 3) * 128 + f;
        mp[o] = s * rp[sidx];
    }
}

// ---------------- assemble conv1 output + gate -> g_h1 (E, 1216) ----------------
__global__ void __launch_bounds__(256) assemble1_kernel(
    const float* __restrict__ t576,
    const float* __restrict__ y0, const float* __restrict__ y1,
    const float* __restrict__ z0, const float* __restrict__ z1,
    float* __restrict__ h1)
{
    int e = blockIdx.x;
    int tid = threadIdx.x;
    const float* T  = t576 + (size_t)e * 576;
    const float* Y0 = y0 + (size_t)e * 512;
    const float* Y1 = y1 + (size_t)e * 512;
    const float* Z0 = z0 + (size_t)e * 384;
    const float* Z1 = z1 + (size_t)e * 384;
    float* H = h1 + (size_t)e * H1_W;

    for (int o = tid; o < H1_W; o += 256) {
        int r = o >> 6, c = o & 63;
        float v;
        if (r < 5)       v = T[r * 64 + c];
        else if (r < 9)  { int j = r - 5;  v = Y0[j * 64 + c] - Y1[256 + j * 64 + c]; }
        else if (r < 13) { int j = r - 9;  v = Y1[j * 64 + c] + Y0[256 + j * 64 + c]; }
        else if (r < 16) { int j = r - 13; v = Z0[j * 64 + c] - Z1[192 + j * 64 + c]; }
        else             { int j = r - 16; v = Z1[j * 64 + c] + Z0[192 + j * 64 + c]; }

        if (r == 0) {
            v = siluf_(v);
        } else {
            int lp;
            if (r < 5)       lp = r - 1;
            else if (r < 9)  lp = r - 5;
            else if (r < 13) lp = r - 9;
            else if (r < 16) lp = r - 12;
            else             lp = r - 15;
            v *= sigmoidf_(T[320 + lp * 64 + c]);
        }
        H[o] = v;
    }
}

// ---------------- assemble conv2 output * envelope -> g_msg2 ----------------
__global__ void __launch_bounds__(256) assemble2_kernel(
    const float* __restrict__ t320,
    const float* __restrict__ y0, const float* __restrict__ y1,
    const float* __restrict__ z0, const float* __restrict__ z1,
    const float* __restrict__ edge_distance,
    float* __restrict__ msg2)
{
    int e = blockIdx.x;
    int tid = threadIdx.x;
    float d = edge_distance[e] * (1.0f / 6.0f);
    float d2 = d * d;
    float d5 = d2 * d2 * d;
    float env = (d < 1.0f) ? (1.0f - 21.0f * d5 + 35.0f * d5 * d - 15.0f * d5 * d2) : 0.0f;

    const float* T  = t320 + (size_t)e * 320;
    const float* Y0 = y0 + (size_t)e * 512;
    const float* Y1 = y1 + (size_t)e * 512;
    const float* Z0 = z0 + (size_t)e * 384;
    const float* Z1 = z1 + (size_t)e * 384;
    float* M = msg2 + (size_t)e * H1_W;

    for (int o = tid; o < H1_W; o += 256) {
        int r = o >> 6, c = o & 63;
        float v;
        if (r < 5)       v = T[r * 64 + c];
        else if (r < 9)  { int j = r - 5;  v = Y0[j * 64 + c] - Y1[256 + j * 64 + c]; }
        else if (r < 13) { int j = r - 9;  v = Y1[j * 64 + c] + Y0[256 + j * 64 + c]; }
        else if (r < 16) { int j = r - 13; v = Z0[j * 64 + c] - Z1[192 + j * 64 + c]; }
        else             { int j = r - 16; v = Z1[j * 64 + c] + Z0[192 + j * 64 + c]; }
        M[o] = v * env;
    }
}

// ---------------- wigner inverse + scatter-add ----------------
__global__ void __launch_bounds__(256) wig_inv_kernel(
    const float* __restrict__ wigner_inv,
    const float* __restrict__ msg2,
    const int* __restrict__ edge_index,
    float* __restrict__ out)
{
    int e = blockIdx.x;
    int tid = threadIdx.x;
    __shared__ float sw[NFULL * NM];   // 475
    __shared__ float sm[NM * 64];      // 1216

    const float* wp = wigner_inv + (size_t)e * (NFULL * NM);
    for (int i = tid; i < NFULL * NM; i += 256) sw[i] = wp[i];
    const float* mp = msg2 + (size_t)e * H1_W;
    for (int i = tid; i < H1_W; i += 256) sm[i] = mp[i];
    __syncthreads();

    int dst = edge_index[NE + e];
    float* op = out + (size_t)dst * (NFULL * 64);
    for (int o = tid; o < NFULL * 64; o += 256) {
        int j = o >> 6, c = o & 63;
        float s = 0.0f;
        const float* wrow = &sw[j * NM];
#pragma unroll
        for (int r = 0; r < NM; r++) s += wrow[r] * sm[r * 64 + c];
        atomicAdd(&op[o], s);
    }
}

// ---------------- host side ----------------
static float* symaddr(const void* sym) {
    void* p = nullptr;
    cudaGetSymbolAddress(&p, sym);
    return (float*)p;
}

static void gemm(const float* A, int lda, const float* W, int N, int K,
                 const float* bias, float* C, int ldc) {
    dim3 grid(N / 64, NE / 64);
    gemm64<<<grid, 256>>>(A, lda, W, N, K, bias, C, ldc);
}

extern "C" void kernel_launch(void* const* d_in, const int* in_sizes, int n_in,
                              void* d_out, int out_size)
{
    const float* x             = (const float*)d_in[0];
    const float* x_edge        = (const float*)d_in[1];
    const float* edge_distance = (const float*)d_in[2];
    const int*   edge_index    = (const int*)  d_in[3];
    const float* wigner        = (const float*)d_in[4];
    const float* wigner_inv    = (const float*)d_in[5];
    const float* rad_w0        = (const float*)d_in[6];
    const float* rad_b0        = (const float*)d_in[7];
    const float* rad_ln0_g     = (const float*)d_in[8];
    const float* rad_ln0_b     = (const float*)d_in[9];
    const float* rad_w1        = (const float*)d_in[10];
    const float* rad_b1        = (const float*)d_in[11];
    const float* rad_ln1_g     = (const float*)d_in[12];
    const float* rad_ln1_b     = (const float*)d_in[13];
    const float* rad_w2        = (const float*)d_in[14];
    const float* rad_b2        = (const float*)d_in[15];
    const float* c1_fc0_w      = (const float*)d_in[16];
    const float* c1_fc0_b      = (const float*)d_in[17];
    const float* c1_m1_w       = (const float*)d_in[18];
    const float* c1_m2_w       = (const float*)d_in[19];
    const float* c2_fc0_w      = (const float*)d_in[20];
    const float* c2_fc0_b      = (const float*)d_in[21];
    const float* c2_m1_w       = (const float*)d_in[22];
    const float* c2_m2_w       = (const float*)d_in[23];
    float* out = (float*)d_out;

    float* p_t64a = symaddr(g_t64a);
    float* p_t64b = symaddr(g_t64b);
    float* p_rad  = symaddr(g_rad);
    float* p_msg1 = symaddr(g_msg1);
    float* p_t576 = symaddr(g_t576);
    float* p_y0   = symaddr(g_y0);
    float* p_y1   = symaddr(g_y1);
    float* p_z0   = symaddr(g_z0);
    float* p_z1   = symaddr(g_z1);
    float* p_h1   = symaddr(g_h1);
    float* p_t320 = symaddr(g_t320);
    float* p_msg2 = symaddr(g_msg2);

    // 0. zero output (poisoned by harness)
    zero_kernel<<<(OUT_ELEMS + 255) / 256, 256>>>(out, OUT_ELEMS);

    // 1. radial MLP
    gemm(x_edge, 128, rad_w0, 64, 128, rad_b0, p_t64a, 64);
    lnsilu_kernel<<<NE, 64>>>(p_t64a, rad_ln0_g, rad_ln0_b);
    gemm(p_t64a, 64, rad_w1, 64, 64, rad_b1, p_t64b, 64);
    lnsilu_kernel<<<NE, 64>>>(p_t64b, rad_ln1_g, rad_ln1_b);
    gemm(p_t64b, 64, rad_w2, RAD_W, 64, rad_b2, p_rad, RAD_W);

    // 2. gather + wigner rotate + radial prescale
    wig_fwd_kernel<<<NE, 256>>>(x, edge_index, wigner, p_rad, p_msg1);

    // 3. conv1 GEMMs
    gemm(p_msg1 + 0,    MSG1_W, c1_fc0_w, 576, 640, c1_fc0_b, p_t576, 576);
    gemm(p_msg1 + 640,  MSG1_W, c1_m1_w,  512, 512, nullptr,  p_y0,   512);
    gemm(p_msg1 + 1152, MSG1_W, c1_m1_w,  512, 512, nullptr,  p_y1,   512);
    gemm(p_msg1 + 1664, MSG1_W, c1_m2_w,  384, 384, nullptr,  p_z0,   384);
    gemm(p_msg1 + 2048, MSG1_W, c1_m2_w,  384, 384, nullptr,  p_z1,   384);

    // 4. SO2 combine + gate
    assemble1_kernel<<<NE, 256>>>(p_t576, p_y0, p_y1, p_z0, p_z1, p_h1);

    // 5. conv2 GEMMs
    gemm(p_h1 + 0,    H1_W, c2_fc0_w, 320, 320, c2_fc0_b, p_t320, 320);
    gemm(p_h1 + 320,  H1_W, c2_m1_w,  512, 256, nullptr,  p_y0,   512);
    gemm(p_h1 + 576,  H1_W, c2_m1_w,  512, 256, nullptr,  p_y1,   512);
    gemm(p_h1 + 832,  H1_W, c2_m2_w,  384, 192, nullptr,  p_z0,   384);
    gemm(p_h1 + 1024, H1_W, c2_m2_w,  384, 192, nullptr,  p_z1,   384);

    // 6. SO2 combine + envelope
    assemble2_kernel<<<NE, 256>>>(p_t320, p_y0, p_y1, p_z0, p_z1, edge_distance, p_msg2);

    // 7. inverse wigner + scatter-add
    wig_inv_kernel<<<NE, 256>>>(wigner_inv, p_msg2, edge_index, out);
}

// round 9
// speedup vs baseline: 1.9584x; 1.9584x over previous
#include <cuda_runtime.h>
#include <cuda_bf16.h>
#include <math.h>
#include <stdint.h>

// ---------------- problem constants ----------------
#define NE 40000
#define EPAD 40064          // 313 * 128
#define MTILES 313
#define NN 10000
#define NFULL 25
#define NM 19
#define MSG1_W 2432
#define H1_W 1216
#define RAD_W 1536
#define OUT_ELEMS (NN * NFULL * 64)

// ---------------- static scratch ----------------
static __device__ float g_t64a[(size_t)NE * 64];
static __device__ float g_t64b[(size_t)NE * 64];
static __device__ float g_rad [(size_t)NE * RAD_W];
static __device__ float g_t576[(size_t)NE * 576];
static __device__ float g_y0  [(size_t)NE * 512];
static __device__ float g_y1  [(size_t)NE * 512];
static __device__ float g_z0  [(size_t)NE * 384];
static __device__ float g_z1  [(size_t)NE * 384];
static __device__ float g_t320[(size_t)NE * 320];
static __device__ float g_msg2[(size_t)NE * H1_W];

static __device__ __nv_bfloat16 g_m1h[(size_t)EPAD * MSG1_W];
static __device__ __nv_bfloat16 g_m1l[(size_t)EPAD * MSG1_W];
static __device__ __nv_bfloat16 g_h1h[(size_t)EPAD * H1_W];
static __device__ __nv_bfloat16 g_h1l[(size_t)EPAD * H1_W];
static __device__ __nv_bfloat16 g_t64h[(size_t)EPAD * 64];
static __device__ __nv_bfloat16 g_t64l[(size_t)EPAD * 64];

#define WTOT 1183744
static __device__ __nv_bfloat16 g_wh[WTOT];
static __device__ __nv_bfloat16 g_wl[WTOT];

// weight offsets within g_wh/g_wl ([N,K] layouts)
#define OFF_C1FC0 0
#define OFF_C1M1  368640
#define OFF_C1M2  630784
#define OFF_C2FC0 778240
#define OFF_C2M1  880640
#define OFF_C2M2  1011712
#define OFF_RADW2 1085440

// ---------------- helpers ----------------
__device__ __forceinline__ float sigmoidf_(float x) { return 1.0f / (1.0f + expf(-x)); }
__device__ __forceinline__ float siluf_(float x)    { return x / (1.0f + expf(-x)); }

__device__ __forceinline__ uint32_t smem_u32(const void* p) {
    uint32_t a;
    asm("{ .reg .u64 t; cvta.to.shared.u64 t, %1; cvt.u32.u64 %0, t; }" : "=r"(a) : "l"(p));
    return a;
}
__device__ __forceinline__ void cpa16(uint32_t dst, const void* src) {
    asm volatile("cp.async.cg.shared.global [%0], [%1], 16;" :: "r"(dst), "l"(src));
}
__device__ __forceinline__ void ldsm4(uint32_t* r, uint32_t addr) {
    asm volatile("ldmatrix.sync.aligned.m8n8.x4.shared.b16 {%0,%1,%2,%3}, [%4];"
        : "=r"(r[0]), "=r"(r[1]), "=r"(r[2]), "=r"(r[3]) : "r"(addr));
}
__device__ __forceinline__ void mma16816(float* d, const uint32_t* a, const uint32_t* b) {
    asm volatile(
        "mma.sync.aligned.m16n8k16.row.col.f32.bf16.bf16.f32 "
        "{%0,%1,%2,%3}, {%4,%5,%6,%7}, {%8,%9}, {%0,%1,%2,%3};"
        : "+f"(d[0]), "+f"(d[1]), "+f"(d[2]), "+f"(d[3])
        : "r"(a[0]), "r"(a[1]), "r"(a[2]), "r"(a[3]), "r"(b[0]), "r"(b[1]));
}

__device__ __forceinline__ void split_store(float v, __nv_bfloat16* hi, __nv_bfloat16* lo, size_t idx) {
    __nv_bfloat16 h = __float2bfloat16(v);
    hi[idx] = h;
    lo[idx] = __float2bfloat16(v - __bfloat162float(h));
}

// ---------------- zero fill ----------------
__global__ void zero_kernel(float* p, int n) {
    int i = blockIdx.x * blockDim.x + threadIdx.x;
    if (i < n) p[i] = 0.0f;
}

// zero pad rows [NE, EPAD) of all bf16 A buffers
__global__ void pad_kernel() {
    int i = blockIdx.x * 256 + threadIdx.x;
    __nv_bfloat16 z = __float2bfloat16(0.0f);
    if (i < 64 * MSG1_W) {
        size_t idx = (size_t)(NE + i / MSG1_W) * MSG1_W + (i % MSG1_W);
        g_m1h[idx] = z; g_m1l[idx] = z;
    }
    if (i < 64 * H1_W) {
        size_t idx = (size_t)(NE + i / H1_W) * H1_W + (i % H1_W);
        g_h1h[idx] = z; g_h1l[idx] = z;
    }
    if (i < 64 * 64) {
        size_t idx = (size_t)(NE + i / 64) * 64 + (i % 64);
        g_t64h[idx] = z; g_t64l[idx] = z;
    }
}

// ---------------- weight convert: fp32 W[K,N] -> bf16 hi/lo [N,K] ----------------
__global__ void convw_kernel(const float* __restrict__ W, int K, int N,
                             __nv_bfloat16* __restrict__ hi, __nv_bfloat16* __restrict__ lo) {
    int i = blockIdx.x * 256 + threadIdx.x;
    if (i < K * N) {
        int n = i / K, k = i - n * K;
        float v = W[(size_t)k * N + n];
        __nv_bfloat16 h = __float2bfloat16(v);
        hi[i] = h;
        lo[i] = __float2bfloat16(v - __bfloat162float(h));
    }
}

// ---------------- SIMT fp32 GEMM (tiny radial layers only) ----------------
__global__ void __launch_bounds__(256) gemm64(
    const float* __restrict__ A, int lda,
    const float* __restrict__ W, int N, int K,
    const float* __restrict__ bias,
    float* __restrict__ C, int ldc)
{
    __shared__ __align__(16) float As[16][68];
    __shared__ __align__(16) float Bs[16][64];

    int tid = threadIdx.x;
    int tx = tid & 15, ty = tid >> 4;
    int m0 = blockIdx.y * 64, n0 = blockIdx.x * 64;
    int ar = tid >> 2, ac = (tid & 3) * 4;
    int wr = tid >> 4, wc = (tid & 15) * 4;
    const float* Ap = A + (size_t)(m0 + ar) * lda + ac;

    float acc[4][4];
#pragma unroll
    for (int i = 0; i < 4; i++)
#pragma unroll
        for (int j = 0; j < 4; j++) acc[i][j] = 0.0f;

    for (int k0 = 0; k0 < K; k0 += 16) {
        float4 av = *(const float4*)(Ap + k0);
        float4 bv = *(const float4*)(W + (size_t)(k0 + wr) * N + n0 + wc);
        As[ac + 0][ar] = av.x; As[ac + 1][ar] = av.y;
        As[ac + 2][ar] = av.z; As[ac + 3][ar] = av.w;
        *(float4*)&Bs[wr][wc] = bv;
        __syncthreads();
#pragma unroll
        for (int kk = 0; kk < 16; kk++) {
            float4 a = *(const float4*)&As[kk][ty * 4];
            float4 b = *(const float4*)&Bs[kk][tx * 4];
            float av_[4] = {a.x, a.y, a.z, a.w};
            float bv_[4] = {b.x, b.y, b.z, b.w};
#pragma unroll
            for (int i = 0; i < 4; i++)
#pragma unroll
                for (int j = 0; j < 4; j++) acc[i][j] += av_[i] * bv_[j];
        }
        __syncthreads();
    }
    float bb[4] = {0.f, 0.f, 0.f, 0.f};
    if (bias) {
#pragma unroll
        for (int j = 0; j < 4; j++) bb[j] = bias[n0 + tx * 4 + j];
    }
#pragma unroll
    for (int i = 0; i < 4; i++) {
        float* Cp = C + (size_t)(m0 + ty * 4 + i) * ldc + n0 + tx * 4;
#pragma unroll
        for (int j = 0; j < 4; j++) Cp[j] = acc[i][j] + bb[j];
    }
}

// ---------------- split-bf16 mma.sync GEMM ----------------
// C[M=EPAD, N] fp32 (rows < NE stored) = (Ah+Al)[:, col0:col0+K] @ (Wh+Wl)^T,  W stored [N,K]
// BM=128, BN=64, BK=32, 256 thr (8 warps 4x2, warp tile 32x32), smem rows 40 bf16 (80B) stride.
#define STG_BYTES 30720       // (128*40 + 128*40 + 64*40 + 64*40) * 2
#define SMEM_MMA  (2 * STG_BYTES)

__global__ void __launch_bounds__(256) mma_gemm(
    const __nv_bfloat16* __restrict__ Ah, const __nv_bfloat16* __restrict__ Al,
    int lda, int col0,
    const __nv_bfloat16* __restrict__ Wh, const __nv_bfloat16* __restrict__ Wl,
    int K, int N,
    const float* __restrict__ bias,
    float* __restrict__ C, int ldc)
{
    extern __shared__ __align__(128) char smem[];
    uint32_t sb = smem_u32(smem);
    int tid = threadIdx.x, lane = tid & 31, wid = tid >> 5;
    int wrow = wid & 3, wcol = wid >> 2;
    int m0 = blockIdx.y << 7, n0 = blockIdx.x << 6;
    int nch = K >> 5;

    float acc[2][4][4];
#pragma unroll
    for (int mt = 0; mt < 2; mt++)
#pragma unroll
        for (int nt = 0; nt < 4; nt++)
#pragma unroll
            for (int j = 0; j < 4; j++) acc[mt][nt][j] = 0.0f;

    auto load = [&](int s, int c) {
        int kc = c << 5;
        uint32_t so = sb + (uint32_t)s * STG_BYTES;
#pragma unroll
        for (int ii = 0; ii < 2; ii++) {          // A: 512 chunks of 16B, 2/thread
            int i = tid + ii * 256;
            int row = i >> 2, ch = (i & 3) << 3;
            size_t g = (size_t)(m0 + row) * lda + col0 + kc + ch;
            uint32_t d = so + (uint32_t)(row * 40 + ch) * 2;
            cpa16(d, Ah + g);
            cpa16(d + 10240, Al + g);
        }
        {                                          // B: 256 chunks, 1/thread
            int row = tid >> 2, ch = (tid & 3) << 3;
            size_t g = (size_t)(n0 + row) * K + kc + ch;
            uint32_t d = so + 20480 + (uint32_t)(row * 40 + ch) * 2;
            cpa16(d, Wh + g);
            cpa16(d + 5120, Wl + g);
        }
        asm volatile("cp.async.commit_group;" ::: "memory");
    };

    load(0, 0);
    for (int c = 0; c < nch; c++) {
        int s = c & 1;
        if (c + 1 < nch) {
            load(s ^ 1, c + 1);
            asm volatile("cp.async.wait_group 1;" ::: "memory");
        } else {
            asm volatile("cp.async.wait_group 0;" ::: "memory");
        }
        __syncthreads();

        uint32_t so = sb + (uint32_t)s * STG_BYTES;
#pragma unroll
        for (int ks = 0; ks < 2; ks++) {
            uint32_t ah[2][4], al[2][4], bh[2][4], bl[2][4];
            int arow = wrow * 32 + (lane & 15);
            uint32_t aoff = so + (uint32_t)(arow * 40 + ks * 16 + ((lane >> 4) << 3)) * 2;
            ldsm4(ah[0], aoff);
            ldsm4(ah[1], aoff + 16 * 80);
            ldsm4(al[0], aoff + 10240);
            ldsm4(al[1], aoff + 10240 + 16 * 80);
            int nrow = wcol * 32 + (lane & 7) + ((lane >> 4) << 3);
            uint32_t boff = so + 20480 +
                            (uint32_t)(nrow * 40 + ks * 16 + (((lane >> 3) & 1) << 3)) * 2;
            ldsm4(bh[0], boff);
            ldsm4(bh[1], boff + 16 * 80);
            ldsm4(bl[0], boff + 5120);
            ldsm4(bl[1], boff + 5120 + 16 * 80);
#pragma unroll
            for (int mt = 0; mt < 2; mt++)
#pragma unroll
                for (int nt = 0; nt < 4; nt++) {
                    const uint32_t* bhp = &bh[nt >> 1][(nt & 1) * 2];
                    const uint32_t* blp = &bl[nt >> 1][(nt & 1) * 2];
                    mma16816(acc[mt][nt], ah[mt], bhp);
                    mma16816(acc[mt][nt], ah[mt], blp);
                    mma16816(acc[mt][nt], al[mt], bhp);
                }
        }
        __syncthreads();
    }

    // epilogue
    int mbase = m0 + wrow * 32, nbase = n0 + wcol * 32;
#pragma unroll
    for (int mt = 0; mt < 2; mt++) {
        int r0 = mbase + mt * 16 + (lane >> 2);
#pragma unroll
        for (int nt = 0; nt < 4; nt++) {
            int cc = nbase + nt * 8 + (lane & 3) * 2;
            float b0 = 0.f, b1 = 0.f;
            if (bias) { b0 = bias[cc]; b1 = bias[cc + 1]; }
            if (r0 < NE) {
                float* Cp = C + (size_t)r0 * ldc + cc;
                Cp[0] = acc[mt][nt][0] + b0;
                Cp[1] = acc[mt][nt][1] + b1;
            }
            if (r0 + 8 < NE) {
                float* Cp = C + (size_t)(r0 + 8) * ldc + cc;
                Cp[0] = acc[mt][nt][2] + b0;
                Cp[1] = acc[mt][nt][3] + b1;
            }
        }
    }
}

// ---------------- LayerNorm + SiLU (optionally emit bf16 hi/lo) ----------------
__global__ void lnsilu_kernel(float* __restrict__ h,
                              const float* __restrict__ g,
                              const float* __restrict__ b,
                              __nv_bfloat16* __restrict__ hi,
                              __nv_bfloat16* __restrict__ lo)
{
    int e = blockIdx.x;
    int t = threadIdx.x;   // 64
    float v = h[(size_t)e * 64 + t];

    __shared__ float red[4];
    float s = v;
#pragma unroll
    for (int o = 16; o > 0; o >>= 1) s += __shfl_xor_sync(0xffffffffu, s, o);
    if ((t & 31) == 0) red[t >> 5] = s;
    __syncthreads();
    float mu = (red[0] + red[1]) * (1.0f / 64.0f);

    float d = v - mu;
    float s2 = d * d;
#pragma unroll
    for (int o = 16; o > 0; o >>= 1) s2 += __shfl_xor_sync(0xffffffffu, s2, o);
    if ((t & 31) == 0) red[2 + (t >> 5)] = s2;
    __syncthreads();
    float var = (red[2] + red[3]) * (1.0f / 64.0f);

    float y = siluf_(d * rsqrtf(var + 1e-5f) * g[t] + b[t]);
    if (hi) split_store(y, hi, lo, (size_t)e * 64 + t);
    else    h[(size_t)e * 64 + t] = y;
}

// ---------------- wigner forward: register-blocked, writes bf16 hi/lo ----------------
__global__ void __launch_bounds__(128) wig_fwd2(
    const float* __restrict__ x,
    const int* __restrict__ edge_index,
    const float* __restrict__ wigner,
    const float* __restrict__ rad,
    __nv_bfloat16* __restrict__ m1h,
    __nv_bfloat16* __restrict__ m1l)
{
    int e = blockIdx.x;
    int tid = threadIdx.x;
    int w = tid >> 5, lane = tid & 31;
    __shared__ float sw[500];
    __shared__ float sx[NFULL * 128];

    int src = edge_index[e];
    int dst = edge_index[NE + e];
    const float* wp = wigner + (size_t)e * (NM * NFULL);
    for (int i = tid; i < NM * NFULL; i += 128) sw[i] = wp[i];

    const float* xs = x + (size_t)src * (NFULL * 64);
    const float* xd = x + (size_t)dst * (NFULL * 64);
    for (int i = tid; i < NFULL * 64; i += 128) {
        int k = i >> 6, c = i & 63;
        sx[k * 128 + c]      = xs[i];
        sx[k * 128 + 64 + c] = xd[i];
    }
    __syncthreads();

    int r0 = w * 5;
    int nr = (w == 3) ? 4 : 5;
    int f0 = lane * 4;
    float acc[5][4];
#pragma unroll
    for (int i = 0; i < 5; i++)
#pragma unroll
        for (int j = 0; j < 4; j++) acc[i][j] = 0.0f;

#pragma unroll
    for (int k = 0; k < NFULL; k++) {
        float4 xv = *(const float4*)&sx[k * 128 + f0];
#pragma unroll
        for (int rr = 0; rr < 5; rr++) {
            float wv = sw[(r0 + rr) * NFULL + k];
            acc[rr][0] += wv * xv.x;
            acc[rr][1] += wv * xv.y;
            acc[rr][2] += wv * xv.z;
            acc[rr][3] += wv * xv.w;
        }
    }

    const float* rp = rad + (size_t)e * RAD_W;
    for (int rr = 0; rr < nr; rr++) {
        int r = r0 + rr;
        int sbase;
        if (r < 5)       sbase = r * 128;
        else if (r < 13) sbase = 640  + ((r - 5) & 3) * 128;
        else             sbase = 1152 + ((r - 13) % 3) * 128;
        size_t o = (size_t)e * MSG1_W + r * 128 + f0;
#pragma unroll
        for (int j = 0; j < 4; j++) {
            float v = acc[rr][j] * rp[sbase + f0 + j];
            split_store(v, m1h, m1l, o + j);
        }
    }
}

// ---------------- assemble conv1 + gate -> h1 (bf16 hi/lo) ----------------
__global__ void __launch_bounds__(256) assemble1_kernel(
    const float* __restrict__ t576,
    const float* __restrict__ y0, const float* __restrict__ y1,
    const float* __restrict__ z0, const float* __restrict__ z1,
    __nv_bfloat16* __restrict__ h1h, __nv_bfloat16* __restrict__ h1l)
{
    int e = blockIdx.x;
    int tid = threadIdx.x;
    const float* T  = t576 + (size_t)e * 576;
    const float* Y0 = y0 + (size_t)e * 512;
    const float* Y1 = y1 + (size_t)e * 512;
    const float* Z0 = z0 + (size_t)e * 384;
    const float* Z1 = z1 + (size_t)e * 384;

    for (int o = tid; o < H1_W; o += 256) {
        int r = o >> 6, c = o & 63;
        float v;
        if (r < 5)       v = T[r * 64 + c];
        else if (r < 9)  { int j = r - 5;  v = Y0[j * 64 + c] - Y1[256 + j * 64 + c]; }
        else if (r < 13) { int j = r - 9;  v = Y1[j * 64 + c] + Y0[256 + j * 64 + c]; }
        else if (r < 16) { int j = r - 13; v = Z0[j * 64 + c] - Z1[192 + j * 64 + c]; }
        else             { int j = r - 16; v = Z1[j * 64 + c] + Z0[192 + j * 64 + c]; }

        if (r == 0) {
            v = siluf_(v);
        } else {
            int lp;
            if (r < 5)       lp = r - 1;
            else if (r < 9)  lp = r - 5;
            else if (r < 13) lp = r - 9;
            else if (r < 16) lp = r - 12;
            else             lp = r - 15;
            v *= sigmoidf_(T[320 + lp * 64 + c]);
        }
        split_store(v, h1h, h1l, (size_t)e * H1_W + o);
    }
}

// ---------------- assemble conv2 * envelope -> msg2 (fp32) ----------------
__global__ void __launch_bounds__(256) assemble2_kernel(
    const float* __restrict__ t320,
    const float* __restrict__ y0, const float* __restrict__ y1,
    const float* __restrict__ z0, const float* __restrict__ z1,
    const float* __restrict__ edge_distance,
    float* __restrict__ msg2)
{
    int e = blockIdx.x;
    int tid = threadIdx.x;
    float d = edge_distance[e] * (1.0f / 6.0f);
    float d2 = d * d;
    float d5 = d2 * d2 * d;
    float env = (d < 1.0f) ? (1.0f - 21.0f * d5 + 35.0f * d5 * d - 15.0f * d5 * d2) : 0.0f;

    const float* T  = t320 + (size_t)e * 320;
    const float* Y0 = y0 + (size_t)e * 512;
    const float* Y1 = y1 + (size_t)e * 512;
    const float* Z0 = z0 + (size_t)e * 384;
    const float* Z1 = z1 + (size_t)e * 384;
    float* M = msg2 + (size_t)e * H1_W;

    for (int o = tid; o < H1_W; o += 256) {
        int r = o >> 6, c = o & 63;
        float v;
        if (r < 5)       v = T[r * 64 + c];
        else if (r < 9)  { int j = r - 5;  v = Y0[j * 64 + c] - Y1[256 + j * 64 + c]; }
        else if (r < 13) { int j = r - 9;  v = Y1[j * 64 + c] + Y0[256 + j * 64 + c]; }
        else if (r < 16) { int j = r - 13; v = Z0[j * 64 + c] - Z1[192 + j * 64 + c]; }
        else             { int j = r - 16; v = Z1[j * 64 + c] + Z0[192 + j * 64 + c]; }
        M[o] = v * env;
    }
}

// ---------------- wigner inverse + scatter-add ----------------
__global__ void __launch_bounds__(256) wig_inv_kernel(
    const float* __restrict__ wigner_inv,
    const float* __restrict__ msg2,
    const int* __restrict__ edge_index,
    float* __restrict__ out)
{
    int e = blockIdx.x;
    int tid = threadIdx.x;
    __shared__ float sw[NFULL * NM];
    __shared__ float sm[NM * 64];

    const float* wp = wigner_inv + (size_t)e * (NFULL * NM);
    for (int i = tid; i < NFULL * NM; i += 256) sw[i] = wp[i];
    const float* mp = msg2 + (size_t)e * H1_W;
    for (int i = tid; i < H1_W; i += 256) sm[i] = mp[i];
    __syncthreads();

    int dst = edge_index[NE + e];
    float* op = out + (size_t)dst * (NFULL * 64);
    for (int o = tid; o < NFULL * 64; o += 256) {
        int j = o >> 6, c = o & 63;
        float s = 0.0f;
        const float* wrow = &sw[j * NM];
#pragma unroll
        for (int r = 0; r < NM; r++) s += wrow[r] * sm[r * 64 + c];
        atomicAdd(&op[o], s);
    }
}

// ---------------- host side ----------------
static float* symaddrf(const void* sym) {
    void* p = nullptr;
    cudaGetSymbolAddress(&p, sym);
    return (float*)p;
}
static __nv_bfloat16* symaddrb(const void* sym) {
    void* p = nullptr;
    cudaGetSymbolAddress(&p, sym);
    return (__nv_bfloat16*)p;
}

static void convw(const float* W, int K, int N, __nv_bfloat16* wh, __nv_bfloat16* wl, int off) {
    int tot = K * N;
    convw_kernel<<<(tot + 255) / 256, 256>>>(W, K, N, wh + off, wl + off);
}

static void mma(const __nv_bfloat16* Ah, const __nv_bfloat16* Al, int lda, int col0,
                const __nv_bfloat16* wh, const __nv_bfloat16* wl, int off,
                int K, int N, const float* bias, float* C, int ldc) {
    dim3 grid(N / 64, MTILES);
    mma_gemm<<<grid, 256, SMEM_MMA>>>(Ah, Al, lda, col0, wh + off, wl + off, K, N, bias, C, ldc);
}

extern "C" void kernel_launch(void* const* d_in, const int* in_sizes, int n_in,
                              void* d_out, int out_size)
{
    const float* x             = (const float*)d_in[0];
    const float* x_edge        = (const float*)d_in[1];
    const float* edge_distance = (const float*)d_in[2];
    const int*   edge_index    = (const int*)  d_in[3];
    const float* wigner        = (const float*)d_in[4];
    const float* wigner_inv    = (const float*)d_in[5];
    const float* rad_w0        = (const float*)d_in[6];
    const float* rad_b0        = (const float*)d_in[7];
    const float* rad_ln0_g     = (const float*)d_in[8];
    const float* rad_ln0_b     = (const float*)d_in[9];
    const float* rad_w1        = (const float*)d_in[10];
    const float* rad_b1        = (const float*)d_in[11];
    const float* rad_ln1_g     = (const float*)d_in[12];
    const float* rad_ln1_b     = (const float*)d_in[13];
    const float* rad_w2        = (const float*)d_in[14];
    const float* rad_b2        = (const float*)d_in[15];
    const float* c1_fc0_w      = (const float*)d_in[16];
    const float* c1_fc0_b      = (const float*)d_in[17];
    const float* c1_m1_w       = (const float*)d_in[18];
    const float* c1_m2_w       = (const float*)d_in[19];
    const float* c2_fc0_w      = (const float*)d_in[20];
    const float* c2_fc0_b      = (const float*)d_in[21];
    const float* c2_m1_w       = (const float*)d_in[22];
    const float* c2_m2_w       = (const float*)d_in[23];
    float* out = (float*)d_out;

    static int smem_set = 0;
    if (!smem_set) {
        cudaFuncSetAttribute(mma_gemm, cudaFuncAttributeMaxDynamicSharedMemorySize, SMEM_MMA);
        smem_set = 1;
    }

    float* p_t64a = symaddrf(g_t64a);
    float* p_t64b = symaddrf(g_t64b);
    float* p_rad  = symaddrf(g_rad);
    float* p_t576 = symaddrf(g_t576);
    float* p_y0   = symaddrf(g_y0);
    float* p_y1   = symaddrf(g_y1);
    float* p_z0   = symaddrf(g_z0);
    float* p_z1   = symaddrf(g_z1);
    float* p_t320 = symaddrf(g_t320);
    float* p_msg2 = symaddrf(g_msg2);
    __nv_bfloat16* p_m1h  = symaddrb(g_m1h);
    __nv_bfloat16* p_m1l  = symaddrb(g_m1l);
    __nv_bfloat16* p_h1h  = symaddrb(g_h1h);
    __nv_bfloat16* p_h1l  = symaddrb(g_h1l);
    __nv_bfloat16* p_t64h = symaddrb(g_t64h);
    __nv_bfloat16* p_t64l = symaddrb(g_t64l);
    __nv_bfloat16* p_wh   = symaddrb(g_wh);
    __nv_bfloat16* p_wl   = symaddrb(g_wl);

    // 0. zero output, pad rows, convert weights (hi/lo, transposed to [N,K])
    zero_kernel<<<(OUT_ELEMS + 255) / 256, 256>>>(out, OUT_ELEMS);
    pad_kernel<<<(64 * MSG1_W + 255) / 256, 256>>>();
    convw(c1_fc0_w, 640, 576,  p_wh, p_wl, OFF_C1FC0);
    convw(c1_m1_w,  512, 512,  p_wh, p_wl, OFF_C1M1);
    convw(c1_m2_w,  384, 384,  p_wh, p_wl, OFF_C1M2);
    convw(c2_fc0_w, 320, 320,  p_wh, p_wl, OFF_C2FC0);
    convw(c2_m1_w,  256, 512,  p_wh, p_wl, OFF_C2M1);
    convw(c2_m2_w,  192, 384,  p_wh, p_wl, OFF_C2M2);
    convw(rad_w2,   64,  1536, p_wh, p_wl, OFF_RADW2);

    // 1. radial MLP (layers 0/1 SIMT, layer 2 tensor)
    {
        dim3 grid(1, NE / 64);
        gemm64<<<grid, 256>>>(x_edge, 128, rad_w0, 64, 128, rad_b0, p_t64a, 64);
        lnsilu_kernel<<<NE, 64>>>(p_t64a, rad_ln0_g, rad_ln0_b, nullptr, nullptr);
        gemm64<<<grid, 256>>>(p_t64a, 64, rad_w1, 64, 64, rad_b1, p_t64b, 64);
        lnsilu_kernel<<<NE, 64>>>(p_t64b, rad_ln1_g, rad_ln1_b, p_t64h, p_t64l);
    }
    mma(p_t64h, p_t64l, 64, 0, p_wh, p_wl, OFF_RADW2, 64, RAD_W, rad_b2, p_rad, RAD_W);

    // 2. gather + wigner rotate + radial prescale -> bf16 hi/lo
    wig_fwd2<<<NE, 128>>>(x, edge_index, wigner, p_rad, p_m1h, p_m1l);

    // 3. conv1 GEMMs (tensor)
    mma(p_m1h, p_m1l, MSG1_W, 0,    p_wh, p_wl, OFF_C1FC0, 640, 576, c1_fc0_b, p_t576, 576);
    mma(p_m1h, p_m1l, MSG1_W, 640,  p_wh, p_wl, OFF_C1M1,  512, 512, nullptr,  p_y0,   512);
    mma(p_m1h, p_m1l, MSG1_W, 1152, p_wh, p_wl, OFF_C1M1,  512, 512, nullptr,  p_y1,   512);
    mma(p_m1h, p_m1l, MSG1_W, 1664, p_wh, p_wl, OFF_C1M2,  384, 384, nullptr,  p_z0,   384);
    mma(p_m1h, p_m1l, MSG1_W, 2048, p_wh, p_wl, OFF_C1M2,  384, 384, nullptr,  p_z1,   384);

    // 4. SO2 combine + gate -> bf16 hi/lo
    assemble1_kernel<<<NE, 256>>>(p_t576, p_y0, p_y1, p_z0, p_z1, p_h1h, p_h1l);

    // 5. conv2 GEMMs (tensor)
    mma(p_h1h, p_h1l, H1_W, 0,    p_wh, p_wl, OFF_C2FC0, 320, 320, c2_fc0_b, p_t320, 320);
    mma(p_h1h, p_h1l, H1_W, 320,  p_wh, p_wl, OFF_C2M1,  256, 512, nullptr,  p_y0,   512);
    mma(p_h1h, p_h1l, H1_W, 576,  p_wh, p_wl, OFF_C2M1,  256, 512, nullptr,  p_y1,   512);
    mma(p_h1h, p_h1l, H1_W, 832,  p_wh, p_wl, OFF_C2M2,  192, 384, nullptr,  p_z0,   384);
    mma(p_h1h, p_h1l, H1_W, 1024, p_wh, p_wl, OFF_C2M2,  192, 384, nullptr,  p_z1,   384);

    // 6. SO2 combine + envelope
    assemble2_kernel<<<NE, 256>>>(p_t320, p_y0, p_y1, p_z0, p_z1, edge_distance, p_msg2);

    // 7. inverse wigner + scatter-add
    wig_inv_kernel<<<NE, 256>>>(wigner_inv, p_msg2, edge_index, out);
}

// round 10
// speedup vs baseline: 2.1857x; 1.1161x over previous
#include <cuda_runtime.h>
#include <cuda_bf16.h>
#include <math.h>
#include <stdint.h>

// ---------------- problem constants ----------------
#define NE 40000
#define EPAD 40064          // 313 * 128
#define MTILES 313
#define NN 10000
#define NFULL 25
#define NM 19
#define MSG1_W 2432
#define H1_W 1216
#define RAD_W 1536
#define OUT_ELEMS (NN * NFULL * 64)

// ---------------- static scratch ----------------
static __device__ float g_t64a[(size_t)NE * 64];
static __device__ float g_t64b[(size_t)NE * 64];
static __device__ float g_rad [(size_t)NE * RAD_W];
static __device__ float g_t576[(size_t)NE * 576];
static __device__ float g_msg2[(size_t)NE * H1_W];

static __device__ __nv_bfloat16 g_m1h[(size_t)EPAD * MSG1_W];
static __device__ __nv_bfloat16 g_m1l[(size_t)EPAD * MSG1_W];
static __device__ __nv_bfloat16 g_h1h[(size_t)EPAD * H1_W];
static __device__ __nv_bfloat16 g_h1l[(size_t)EPAD * H1_W];
static __device__ __nv_bfloat16 g_t64h[(size_t)EPAD * 64];
static __device__ __nv_bfloat16 g_t64l[(size_t)EPAD * 64];

// weight store: [Npad, K] transposed, hi/lo
#define OFF_C1FC0 0          //  640 x  640
#define OFF_C1M1C 409600     //  512 x 1024 (complex-merged)
#define OFF_C1M2C 933888     //  384 x  768
#define OFF_C2FC0 1228800    //  384 x  320
#define OFF_C2M1C 1351680    //  512 x  512
#define OFF_C2M2C 1613824    //  384 x  384
#define OFF_RADW2 1761280    // 1536 x   64
#define WTOT      1859584
static __device__ __nv_bfloat16 g_wh[WTOT];
static __device__ __nv_bfloat16 g_wl[WTOT];

// ---------------- helpers ----------------
__device__ __forceinline__ float sigmoidf_(float x) { return 1.0f / (1.0f + expf(-x)); }
__device__ __forceinline__ float siluf_(float x)    { return x / (1.0f + expf(-x)); }
__device__ __forceinline__ float envf_(float dist) {
    float d = dist * (1.0f / 6.0f);
    float d2 = d * d;
    float d5 = d2 * d2 * d;
    return (d < 1.0f) ? (1.0f - 21.0f * d5 + 35.0f * d5 * d - 15.0f * d5 * d2) : 0.0f;
}

__device__ __forceinline__ uint32_t smem_u32(const void* p) {
    uint32_t a;
    asm("{ .reg .u64 t; cvta.to.shared.u64 t, %1; cvt.u32.u64 %0, t; }" : "=r"(a) : "l"(p));
    return a;
}
__device__ __forceinline__ void cpa16(uint32_t dst, const void* src) {
    asm volatile("cp.async.cg.shared.global [%0], [%1], 16;" :: "r"(dst), "l"(src));
}
__device__ __forceinline__ void ldsm4(uint32_t* r, uint32_t addr) {
    asm volatile("ldmatrix.sync.aligned.m8n8.x4.shared.b16 {%0,%1,%2,%3}, [%4];"
        : "=r"(r[0]), "=r"(r[1]), "=r"(r[2]), "=r"(r[3]) : "r"(addr));
}
__device__ __forceinline__ void mma16816(float* d, const uint32_t* a, const uint32_t* b) {
    asm volatile(
        "mma.sync.aligned.m16n8k16.row.col.f32.bf16.bf16.f32 "
        "{%0,%1,%2,%3}, {%4,%5,%6,%7}, {%8,%9}, {%0,%1,%2,%3};"
        : "+f"(d[0]), "+f"(d[1]), "+f"(d[2]), "+f"(d[3])
        : "r"(a[0]), "r"(a[1]), "r"(a[2]), "r"(a[3]), "r"(b[0]), "r"(b[1]));
}
__device__ __forceinline__ void split_store(float v, __nv_bfloat16* hi, __nv_bfloat16* lo, size_t idx) {
    __nv_bfloat16 h = __float2bfloat16(v);
    hi[idx] = h;
    lo[idx] = __float2bfloat16(v - __bfloat162float(h));
}

// ---------------- zero fill ----------------
__global__ void zero_kernel(float* p, int n) {
    int i = blockIdx.x * blockDim.x + threadIdx.x;
    if (i < n) p[i] = 0.0f;
}

// zero pad rows [NE, EPAD) of bf16 A buffers
__global__ void pad_kernel() {
    int i = blockIdx.x * 256 + threadIdx.x;
    __nv_bfloat16 z = __float2bfloat16(0.0f);
    if (i < 64 * MSG1_W) {
        size_t idx = (size_t)(NE + i / MSG1_W) * MSG1_W + (i % MSG1_W);
        g_m1h[idx] = z; g_m1l[idx] = z;
    }
    if (i < 64 * H1_W) {
        size_t idx = (size_t)(NE + i / H1_W) * H1_W + (i % H1_W);
        g_h1h[idx] = z; g_h1l[idx] = z;
    }
    if (i < 64 * 64) {
        size_t idx = (size_t)(NE + i / 64) * 64 + (i % 64);
        g_t64h[idx] = z; g_t64l[idx] = z;
    }
}

// ---------------- weight converts ----------------
// plain transpose with N padding: fp32 W[K,N] -> bf16 hi/lo [Npad,K]
__global__ void convw_t(const float* __restrict__ W, int K, int N, int Npad,
                        __nv_bfloat16* __restrict__ hi, __nv_bfloat16* __restrict__ lo) {
    int i = blockIdx.x * 256 + threadIdx.x;
    if (i < Npad * K) {
        int n = i / K, k = i - n * K;
        float v = (n < N) ? W[(size_t)k * N + n] : 0.0f;
        __nv_bfloat16 h = __float2bfloat16(v);
        hi[i] = h;
        lo[i] = __float2bfloat16(v - __bfloat162float(h));
    }
}

// complex-merged: W (K2, 2*half) -> Wc (2*K2, 2*half) = [[Wr,Wi],[-Wi,Wr]],
// stored transposed hi/lo [Nc=2*half, Kc=2*K2]
__global__ void convw_c(const float* __restrict__ W, int K2, int half,
                        __nv_bfloat16* __restrict__ hi, __nv_bfloat16* __restrict__ lo) {
    int Kc = 2 * K2, Nc = 2 * half;
    int i = blockIdx.x * 256 + threadIdx.x;
    if (i < Nc * Kc) {
        int n = i / Kc, k = i - n * Kc;
        float v;
        if (k < K2)           v = W[(size_t)k * Nc + n];                         // [Wr, Wi]
        else if (n < half)    v = -W[(size_t)(k - K2) * Nc + half + n];          // -Wi
        else                  v = W[(size_t)(k - K2) * Nc + (n - half)];         // Wr
        __nv_bfloat16 h = __float2bfloat16(v);
        hi[i] = h;
        lo[i] = __float2bfloat16(v - __bfloat162float(h));
    }
}

// ---------------- SIMT fp32 GEMM (tiny radial layers only) ----------------
__global__ void __launch_bounds__(256) gemm64(
    const float* __restrict__ A, int lda,
    const float* __restrict__ W, int N, int K,
    const float* __restrict__ bias,
    float* __restrict__ C, int ldc)
{
    __shared__ __align__(16) float As[16][68];
    __shared__ __align__(16) float Bs[16][64];

    int tid = threadIdx.x;
    int tx = tid & 15, ty = tid >> 4;
    int m0 = blockIdx.y * 64, n0 = blockIdx.x * 64;
    int ar = tid >> 2, ac = (tid & 3) * 4;
    int wr = tid >> 4, wc = (tid & 15) * 4;
    const float* Ap = A + (size_t)(m0 + ar) * lda + ac;

    float acc[4][4];
#pragma unroll
    for (int i = 0; i < 4; i++)
#pragma unroll
        for (int j = 0; j < 4; j++) acc[i][j] = 0.0f;

    for (int k0 = 0; k0 < K; k0 += 16) {
        float4 av = *(const float4*)(Ap + k0);
        float4 bv = *(const float4*)(W + (size_t)(k0 + wr) * N + n0 + wc);
        As[ac + 0][ar] = av.x; As[ac + 1][ar] = av.y;
        As[ac + 2][ar] = av.z; As[ac + 3][ar] = av.w;
        *(float4*)&Bs[wr][wc] = bv;
        __syncthreads();
#pragma unroll
        for (int kk = 0; kk < 16; kk++) {
            float4 a = *(const float4*)&As[kk][ty * 4];
            float4 b = *(const float4*)&Bs[kk][tx * 4];
            float av_[4] = {a.x, a.y, a.z, a.w};
            float bv_[4] = {b.x, b.y, b.z, b.w};
#pragma unroll
            for (int i = 0; i < 4; i++)
#pragma unroll
                for (int j = 0; j < 4; j++) acc[i][j] += av_[i] * bv_[j];
        }
        __syncthreads();
    }
    float bb[4] = {0.f, 0.f, 0.f, 0.f};
    if (bias) {
#pragma unroll
        for (int j = 0; j < 4; j++) bb[j] = bias[n0 + tx * 4 + j];
    }
#pragma unroll
    for (int i = 0; i < 4; i++) {
        float* Cp = C + (size_t)(m0 + ty * 4 + i) * ldc + n0 + tx * 4;
#pragma unroll
        for (int j = 0; j < 4; j++) Cp[j] = acc[i][j] + bb[j];
    }
}

// ---------------- split-bf16 mma.sync GEMM, BM=128 BN=128 BK=32 ----------------
// modes: 0 = fp32 C (+bias), cols < Nreal
//        1 = conv1 gated bf16 hi/lo -> h1 (mtype 1: rowbase 5 / 2: rowbase 13)
//        2 = conv2 envelope fp32 -> msg2 (mtype 0: identity cols<Nreal (+bias); 1/2: row remap)
#define STG_BYTES 40960     // (128*40 A hi+lo + 128*40 B hi+lo) * 2B
#define SMEM_MMA  (2 * STG_BYTES)

__global__ void __launch_bounds__(256) mma_gemm(
    const __nv_bfloat16* __restrict__ Ah, const __nv_bfloat16* __restrict__ Al,
    int lda, int col0,
    const __nv_bfloat16* __restrict__ Wh, const __nv_bfloat16* __restrict__ Wl,
    int K, int mode, int mtype, int Nreal,
    const float* __restrict__ bias,
    const float* __restrict__ edge_distance,
    const float* __restrict__ gsrc,           // t576 for gating
    float* __restrict__ Cf, int ldc,
    __nv_bfloat16* __restrict__ Ch, __nv_bfloat16* __restrict__ Cl)
{
    extern __shared__ __align__(128) char smem[];
    uint32_t sb = smem_u32(smem);
    int tid = threadIdx.x, lane = tid & 31, wid = tid >> 5;
    int wrow = wid & 1, wcol = wid >> 1;
    int m0 = blockIdx.y << 7, n0 = blockIdx.x << 7;
    int nch = K >> 5;

    float acc[4][4][4];
#pragma unroll
    for (int mt = 0; mt < 4; mt++)
#pragma unroll
        for (int nt = 0; nt < 4; nt++)
#pragma unroll
            for (int j = 0; j < 4; j++) acc[mt][nt][j] = 0.0f;

    auto load = [&](int s, int c) {
        int kc = c << 5;
        uint32_t so = sb + (uint32_t)s * STG_BYTES;
#pragma unroll
        for (int ii = 0; ii < 2; ii++) {
            int i = tid + ii * 256;                 // 0..511
            int row = i >> 2, ch = (i & 3) << 3;
            size_t gA = (size_t)(m0 + row) * lda + col0 + kc + ch;
            uint32_t d = so + (uint32_t)(row * 40 + ch) * 2;
            cpa16(d, Ah + gA);
            cpa16(d + 10240, Al + gA);
            size_t gB = (size_t)(n0 + row) * K + kc + ch;
            uint32_t d2 = so + 20480 + (uint32_t)(row * 40 + ch) * 2;
            cpa16(d2, Wh + gB);
            cpa16(d2 + 10240, Wl + gB);
        }
        asm volatile("cp.async.commit_group;" ::: "memory");
    };

    load(0, 0);
    for (int c = 0; c < nch; c++) {
        int s = c & 1;
        if (c + 1 < nch) {
            load(s ^ 1, c + 1);
            asm volatile("cp.async.wait_group 1;" ::: "memory");
        } else {
            asm volatile("cp.async.wait_group 0;" ::: "memory");
        }
        __syncthreads();

        uint32_t so = sb + (uint32_t)s * STG_BYTES;
#pragma unroll
        for (int ks = 0; ks < 2; ks++) {
            uint32_t ah[4][4], al[4][4], bh[2][4], bl[2][4];
            int arow = wrow * 64 + (lane & 15);
            uint32_t aoff = so + (uint32_t)(arow * 40 + ks * 16 + ((lane >> 4) << 3)) * 2;
#pragma unroll
            for (int mt = 0; mt < 4; mt++) {
                ldsm4(ah[mt], aoff + mt * 16 * 80);
                ldsm4(al[mt], aoff + 10240 + mt * 16 * 80);
            }
            int nrow = wcol * 32 + (lane & 7) + ((lane >> 4) << 3);
            uint32_t boff = so + 20480 +
                            (uint32_t)(nrow * 40 + ks * 16 + (((lane >> 3) & 1) << 3)) * 2;
            ldsm4(bh[0], boff);
            ldsm4(bh[1], boff + 16 * 80);
            ldsm4(bl[0], boff + 10240);
            ldsm4(bl[1], boff + 10240 + 16 * 80);
#pragma unroll
            for (int mt = 0; mt < 4; mt++)
#pragma unroll
                for (int nt = 0; nt < 4; nt++) {
                    const uint32_t* bhp = &bh[nt >> 1][(nt & 1) * 2];
                    const uint32_t* blp = &bl[nt >> 1][(nt & 1) * 2];
                    mma16816(acc[mt][nt], ah[mt], bhp);
                    mma16816(acc[mt][nt], ah[mt], blp);
                    mma16816(acc[mt][nt], al[mt], bhp);
                }
        }
        __syncthreads();
    }

    // ---------------- fused epilogue ----------------
    int mbase = m0 + wrow * 64;
    int ncb = n0 + wcol * 32 + (lane & 3) * 2;
#pragma unroll
    for (int mt = 0; mt < 4; mt++) {
#pragma unroll
        for (int half = 0; half < 2; half++) {
            int row = mbase + mt * 16 + (lane >> 2) + half * 8;
            if (row >= NE) continue;
            float env = 0.0f;
            if (mode == 2) env = envf_(edge_distance[row]);
#pragma unroll
            for (int nt = 0; nt < 4; nt++) {
                int ccol = ncb + nt * 8;
                float v0 = acc[mt][nt][half * 2 + 0];
                float v1 = acc[mt][nt][half * 2 + 1];
                if (mode == 0) {
                    if (ccol < Nreal) {
                        float b0 = 0.f, b1 = 0.f;
                        if (bias) { b0 = bias[ccol]; b1 = bias[ccol + 1]; }
                        float* Cp = Cf + (size_t)row * ldc + ccol;
                        Cp[0] = v0 + b0;
                        Cp[1] = v1 + b1;
                    }
                } else if (mode == 1) {
                    int j = ccol >> 6, cc = ccol & 63;
                    int hrow = ((mtype == 1) ? 5 : 13) + j;
                    int lp = (mtype == 1) ? (j & 3) : ((j < 3) ? j + 1 : j - 2);
                    const float* gp = gsrc + (size_t)row * 576 + 320 + lp * 64 + cc;
                    float g0 = sigmoidf_(gp[0]);
                    float g1 = sigmoidf_(gp[1]);
                    size_t o = (size_t)row * H1_W + hrow * 64 + cc;
                    split_store(v0 * g0, Ch, Cl, o);
                    split_store(v1 * g1, Ch, Cl, o + 1);
                } else {
                    int off;
                    float b0 = 0.f, b1 = 0.f;
                    if (mtype == 0) {
                        if (ccol >= Nreal) continue;
                        off = ccol;
                        if (bias) { b0 = bias[ccol]; b1 = bias[ccol + 1]; }
                    } else {
                        int j = ccol >> 6, cc = ccol & 63;
                        int hrow = ((mtype == 1) ? 5 : 13) + j;
                        off = hrow * 64 + cc;
                    }
                    float* Mp = Cf + (size_t)row * H1_W + off;
                    Mp[0] = (v0 + b0) * env;
                    Mp[1] = (v1 + b1) * env;
                }
            }
        }
    }
}

// ---------------- LayerNorm + SiLU (optionally emit bf16 hi/lo) ----------------
__global__ void lnsilu_kernel(float* __restrict__ h,
                              const float* __restrict__ g,
                              const float* __restrict__ b,
                              __nv_bfloat16* __restrict__ hi,
                              __nv_bfloat16* __restrict__ lo)
{
    int e = blockIdx.x;
    int t = threadIdx.x;   // 64
    float v = h[(size_t)e * 64 + t];

    __shared__ float red[4];
    float s = v;
#pragma unroll
    for (int o = 16; o > 0; o >>= 1) s += __shfl_xor_sync(0xffffffffu, s, o);
    if ((t & 31) == 0) red[t >> 5] = s;
    __syncthreads();
    float mu = (red[0] + red[1]) * (1.0f / 64.0f);

    float d = v - mu;
    float s2 = d * d;
#pragma unroll
    for (int o = 16; o > 0; o >>= 1) s2 += __shfl_xor_sync(0xffffffffu, s2, o);
    if ((t & 31) == 0) red[2 + (t >> 5)] = s2;
    __syncthreads();
    float var = (red[2] + red[3]) * (1.0f / 64.0f);

    float y = siluf_(d * rsqrtf(var + 1e-5f) * g[t] + b[t]);
    if (hi) split_store(y, hi, lo, (size_t)e * 64 + t);
    else    h[(size_t)e * 64 + t] = y;
}

// ---------------- wigner forward: register-blocked, writes bf16 hi/lo ----------------
__global__ void __launch_bounds__(128) wig_fwd2(
    const float* __restrict__ x,
    const int* __restrict__ edge_index,
    const float* __restrict__ wigner,
    const float* __restrict__ rad,
    __nv_bfloat16* __restrict__ m1h,
    __nv_bfloat16* __restrict__ m1l)
{
    int e = blockIdx.x;
    int tid = threadIdx.x;
    int w = tid >> 5, lane = tid & 31;
    __shared__ float sw[500];
    __shared__ float sx[NFULL * 128];

    int src = edge_index[e];
    int dst = edge_index[NE + e];
    const float* wp = wigner + (size_t)e * (NM * NFULL);
    for (int i = tid; i < NM * NFULL; i += 128) sw[i] = wp[i];

    const float* xs = x + (size_t)src * (NFULL * 64);
    const float* xd = x + (size_t)dst * (NFULL * 64);
    for (int i = tid; i < NFULL * 64; i += 128) {
        int k = i >> 6, c = i & 63;
        sx[k * 128 + c]      = xs[i];
        sx[k * 128 + 64 + c] = xd[i];
    }
    __syncthreads();

    int r0 = w * 5;
    int nr = (w == 3) ? 4 : 5;
    int f0 = lane * 4;
    float acc[5][4];
#pragma unroll
    for (int i = 0; i < 5; i++)
#pragma unroll
        for (int j = 0; j < 4; j++) acc[i][j] = 0.0f;

#pragma unroll
    for (int k = 0; k < NFULL; k++) {
        float4 xv = *(const float4*)&sx[k * 128 + f0];
#pragma unroll
        for (int rr = 0; rr < 5; rr++) {
            float wv = sw[(r0 + rr) * NFULL + k];
            acc[rr][0] += wv * xv.x;
            acc[rr][1] += wv * xv.y;
            acc[rr][2] += wv * xv.z;
            acc[rr][3] += wv * xv.w;
        }
    }

    const float* rp = rad + (size_t)e * RAD_W;
    for (int rr = 0; rr < nr; rr++) {
        int r = r0 + rr;
        int sbase;
        if (r < 5)       sbase = r * 128;
        else if (r < 13) sbase = 640  + ((r - 5) & 3) * 128;
        else             sbase = 1152 + ((r - 13) % 3) * 128;
        size_t o = (size_t)e * MSG1_W + r * 128 + f0;
#pragma unroll
        for (int j = 0; j < 4; j++) {
            float v = acc[rr][j] * rp[sbase + f0 + j];
            split_store(v, m1h, m1l, o + j);
        }
    }
}

// ---------------- assemble conv1 rows 0..4 (silu + gated l=1..4 scalars) ----------------
__global__ void __launch_bounds__(256) assemble1a_kernel(
    const float* __restrict__ t576,
    __nv_bfloat16* __restrict__ h1h, __nv_bfloat16* __restrict__ h1l)
{
    int e = blockIdx.x;
    int tid = threadIdx.x;
    const float* T = t576 + (size_t)e * 576;
    for (int o = tid; o < 320; o += 256) {
        int r = o >> 6, c = o & 63;
        float v = T[o];
        if (r == 0) v = siluf_(v);
        else        v *= sigmoidf_(T[320 + (r - 1) * 64 + c]);
        split_store(v, h1h, h1l, (size_t)e * H1_W + o);
    }
}

// ---------------- wigner inverse + scatter-add ----------------
__global__ void __launch_bounds__(256) wig_inv_kernel(
    const float* __restrict__ wigner_inv,
    const float* __restrict__ msg2,
    const int* __restrict__ edge_index,
    float* __restrict__ out)
{
    int e = blockIdx.x;
    int tid = threadIdx.x;
    __shared__ float sw[NFULL * NM];
    __shared__ float sm[NM * 64];

    const float* wp = wigner_inv + (size_t)e * (NFULL * NM);
    for (int i = tid; i < NFULL * NM; i += 256) sw[i] = wp[i];
    const float* mp = msg2 + (size_t)e * H1_W;
    for (int i = tid; i < H1_W; i += 256) sm[i] = mp[i];
    __syncthreads();

    int dst = edge_index[NE + e];
    float* op = out + (size_t)dst * (NFULL * 64);
    for (int o = tid; o < NFULL * 64; o += 256) {
        int j = o >> 6, c = o & 63;
        float s = 0.0f;
        const float* wrow = &sw[j * NM];
#pragma unroll
        for (int r = 0; r < NM; r++) s += wrow[r] * sm[r * 64 + c];
        atomicAdd(&op[o], s);
    }
}

// ---------------- host side ----------------
static float* symaddrf(const void* sym) {
    void* p = nullptr;
    cudaGetSymbolAddress(&p, sym);
    return (float*)p;
}
static __nv_bfloat16* symaddrb(const void* sym) {
    void* p = nullptr;
    cudaGetSymbolAddress(&p, sym);
    return (__nv_bfloat16*)p;
}

extern "C" void kernel_launch(void* const* d_in, const int* in_sizes, int n_in,
                              void* d_out, int out_size)
{
    const float* x             = (const float*)d_in[0];
    const float* x_edge        = (const float*)d_in[1];
    const float* edge_distance = (const float*)d_in[2];
    const int*   edge_index    = (const int*)  d_in[3];
    const float* wigner        = (const float*)d_in[4];
    const float* wigner_inv    = (const float*)d_in[5];
    const float* rad_w0        = (const float*)d_in[6];
    const float* rad_b0        = (const float*)d_in[7];
    const float* rad_ln0_g     = (const float*)d_in[8];
    const float* rad_ln0_b     = (const float*)d_in[9];
    const float* rad_w1        = (const float*)d_in[10];
    const float* rad_b1        = (const float*)d_in[11];
    const float* rad_ln1_g     = (const float*)d_in[12];
    const float* rad_ln1_b     = (const float*)d_in[13];
    const float* rad_w2        = (const float*)d_in[14];
    const float* rad_b2        = (const float*)d_in[15];
    const float* c1_fc0_w      = (const float*)d_in[16];
    const float* c1_fc0_b      = (const float*)d_in[17];
    const float* c1_m1_w       = (const float*)d_in[18];
    const float* c1_m2_w       = (const float*)d_in[19];
    const float* c2_fc0_w      = (const float*)d_in[20];
    const float* c2_fc0_b      = (const float*)d_in[21];
    const float* c2_m1_w       = (const float*)d_in[22];
    const float* c2_m2_w       = (const float*)d_in[23];
    float* out = (float*)d_out;

    static int smem_set = 0;
    if (!smem_set) {
        cudaFuncSetAttribute(mma_gemm, cudaFuncAttributeMaxDynamicSharedMemorySize, SMEM_MMA);
        smem_set = 1;
    }

    float* p_t64a = symaddrf(g_t64a);
    float* p_t64b = symaddrf(g_t64b);
    float* p_rad  = symaddrf(g_rad);
    float* p_t576 = symaddrf(g_t576);
    float* p_msg2 = symaddrf(g_msg2);
    __nv_bfloat16* p_m1h  = symaddrb(g_m1h);
    __nv_bfloat16* p_m1l  = symaddrb(g_m1l);
    __nv_bfloat16* p_h1h  = symaddrb(g_h1h);
    __nv_bfloat16* p_h1l  = symaddrb(g_h1l);
    __nv_bfloat16* p_t64h = symaddrb(g_t64h);
    __nv_bfloat16* p_t64l = symaddrb(g_t64l);
    __nv_bfloat16* p_wh   = symaddrb(g_wh);
    __nv_bfloat16* p_wl   = symaddrb(g_wl);

    // 0. zero output, pad rows, build weights
    zero_kernel<<<(OUT_ELEMS + 255) / 256, 256>>>(out, OUT_ELEMS);
    pad_kernel<<<(64 * MSG1_W + 255) / 256, 256>>>();

    convw_t<<<(640 * 640 + 255) / 256, 256>>>(c1_fc0_w, 640, 576, 640,
                                              p_wh + OFF_C1FC0, p_wl + OFF_C1FC0);
    convw_c<<<(512 * 1024 + 255) / 256, 256>>>(c1_m1_w, 512, 256,
                                               p_wh + OFF_C1M1C, p_wl + OFF_C1M1C);
    convw_c<<<(384 * 768 + 255) / 256, 256>>>(c1_m2_w, 384, 192,
                                              p_wh + OFF_C1M2C, p_wl + OFF_C1M2C);
    convw_t<<<(384 * 320 + 255) / 256, 256>>>(c2_fc0_w, 320, 320, 384,
                                              p_wh + OFF_C2FC0, p_wl + OFF_C2FC0);
    convw_c<<<(512 * 512 + 255) / 256, 256>>>(c2_m1_w, 256, 256,
                                              p_wh + OFF_C2M1C, p_wl + OFF_C2M1C);
    convw_c<<<(384 * 384 + 255) / 256, 256>>>(c2_m2_w, 192, 192,
                                              p_wh + OFF_C2M2C, p_wl + OFF_C2M2C);
    convw_t<<<(1536 * 64 + 255) / 256, 256>>>(rad_w2, 64, 1536, 1536,
                                              p_wh + OFF_RADW2, p_wl + OFF_RADW2);

    // 1. radial MLP (layers 0/1 SIMT, layer 2 tensor)
    {
        dim3 grid(1, NE / 64);
        gemm64<<<grid, 256>>>(x_edge, 128, rad_w0, 64, 128, rad_b0, p_t64a, 64);
        lnsilu_kernel<<<NE, 64>>>(p_t64a, rad_ln0_g, rad_ln0_b, nullptr, nullptr);
        gemm64<<<grid, 256>>>(p_t64a, 64, rad_w1, 64, 64, rad_b1, p_t64b, 64);
        lnsilu_kernel<<<NE, 64>>>(p_t64b, rad_ln1_g, rad_ln1_b, p_t64h, p_t64l);
    }
    mma_gemm<<<dim3(12, MTILES), 256, SMEM_MMA>>>(
        p_t64h, p_t64l, 64, 0, p_wh + OFF_RADW2, p_wl + OFF_RADW2, 64,
        0, 0, 1536, rad_b2, nullptr, nullptr, p_rad, RAD_W, nullptr, nullptr);

    // 2. gather + wigner rotate + radial prescale -> bf16 hi/lo
    wig_fwd2<<<NE, 128>>>(x, edge_index, wigner, p_rad, p_m1h, p_m1l);

    // 3. conv1: fc0 -> t576 (fp32), then gated complex m-convs -> h1 (bf16)
    mma_gemm<<<dim3(5, MTILES), 256, SMEM_MMA>>>(
        p_m1h, p_m1l, MSG1_W, 0, p_wh + OFF_C1FC0, p_wl + OFF_C1FC0, 640,
        0, 0, 576, c1_fc0_b, nullptr, nullptr, p_t576, 576, nullptr, nullptr);
    assemble1a_kernel<<<NE, 256>>>(p_t576, p_h1h, p_h1l);
    mma_gemm<<<dim3(4, MTILES), 256, SMEM_MMA>>>(
        p_m1h, p_m1l, MSG1_W, 640, p_wh + OFF_C1M1C, p_wl + OFF_C1M1C, 1024,
        1, 1, 512, nullptr, nullptr, p_t576, nullptr, 0, p_h1h, p_h1l);
    mma_gemm<<<dim3(3, MTILES), 256, SMEM_MMA>>>(
        p_m1h, p_m1l, MSG1_W, 1664, p_wh + OFF_C1M2C, p_wl + OFF_C1M2C, 768,
        1, 2, 384, nullptr, nullptr, p_t576, nullptr, 0, p_h1h, p_h1l);

    // 4. conv2: envelope fused, write msg2 directly
    mma_gemm<<<dim3(3, MTILES), 256, SMEM_MMA>>>(
        p_h1h, p_h1l, H1_W, 0, p_wh + OFF_C2FC0, p_wl + OFF_C2FC0, 320,
        2, 0, 320, c2_fc0_b, edge_distance, nullptr, p_msg2, H1_W, nullptr, nullptr);
    mma_gemm<<<dim3(4, MTILES), 256, SMEM_MMA>>>(
        p_h1h, p_h1l, H1_W, 320, p_wh + OFF_C2M1C, p_wl + OFF_C2M1C, 512,
        2, 1, 512, nullptr, edge_distance, nullptr, p_msg2, H1_W, nullptr, nullptr);
    mma_gemm<<<dim3(3, MTILES), 256, SMEM_MMA>>>(
        p_h1h, p_h1l, H1_W, 832, p_wh + OFF_C2M2C, p_wl + OFF_C2M2C, 384,
        2, 2, 384, nullptr, edge_distance, nullptr, p_msg2, H1_W, nullptr, nullptr);

    // 5. inverse wigner + scatter-add
    wig_inv_kernel<<<NE, 256>>>(wigner_inv, p_msg2, edge_index, out);
}